// round 16
// baseline (speedup 1.0000x reference)
#include <cuda_runtime.h>
#include <cuda_bf16.h>
#include <math.h>

#define T_ 256
#define B_ 16
#define E_ 512
#define H_ 2048
#define N_ 14839
#define U_ 48
#define G4H 8192
#define KA 2560
#define KHF 1280
#define EPS_ 1e-6f
#define NT 256
#define GRID 256
#define APAD 2568
#define WPAD 72
#define SMEM_DYN ((16*APAD + 2*32*WPAD) * 2)

/* ---------------- scratch ---------------- */
__device__ float g_xh_m[T_*B_*E_];
__device__ float g_xh_c[T_*B_*E_];
__device__ float g_emb[U_*B_*E_];
__device__ float g_eg[(size_t)U_*B_*G4H];
__device__ float g_h[2][B_*H_];
__device__ float g_c[2][B_*H_];
__device__ float g_alpha[2][T_*B_];
__device__ float g_sm[B_*E_];
__device__ float g_sc[B_*E_];
__device__ float g_p[T_*B_];
__device__ float g_u[T_*B_];
__device__ float g_beta[T_*B_];
__device__ float g_scall[U_*B_*2*E_];
__device__ float g_wpT[H_*E_];
__device__ float g_comb[2*E_*H_];
__device__ __nv_bfloat16 g_wcomb[(size_t)G4H*KA];  /* gate-interleaved rows: r' = 4k+gate */
__device__ __nv_bfloat16 g_actbf[B_*KA];

/* grid barrier state */
__device__ unsigned g_cnt = 0;
__device__ volatile unsigned g_gen = 0;

__device__ __forceinline__ void gbar() {
    __syncthreads();
    if (threadIdx.x == 0) {
        unsigned gen = g_gen;
        __threadfence();
        if (atomicAdd(&g_cnt, 1u) == gridDim.x - 1u) {
            g_cnt = 0;
            __threadfence();
            g_gen = gen + 1u;
        } else {
            while (g_gen == gen) __nanosleep(32);
        }
        __threadfence();
    }
    __syncthreads();
}

__device__ __forceinline__ float sigm(float x) { return 1.f / (1.f + expf(-x)); }
__device__ __forceinline__ unsigned tf32c(float x) {
    unsigned r; asm("cvt.rna.tf32.f32 %0, %1;" : "=r"(r) : "f"(x)); return r;
}
__device__ __forceinline__ float2 tanh2(float e0, float e1) {
    unsigned pk;
    asm("cvt.rn.f16x2.f32 %0, %1, %2;" : "=r"(pk) : "f"(e1), "f"(e0));
    asm("tanh.approx.f16x2 %0, %0;" : "+r"(pk));
    float t0, t1;
    asm("{.reg .f16 lo, hi;\n\t"
        "mov.b32 {lo, hi}, %2;\n\t"
        "cvt.f32.f16 %0, lo;\n\t"
        "cvt.f32.f16 %1, hi;}"
        : "=f"(t0), "=f"(t1) : "r"(pk));
    return make_float2(t0, t1);
}

/* ---------------- init ---------------- */
__global__ void init_state(float* h, float* c, float* alpha, __nv_bfloat16* actbf) {
    int i = blockIdx.x * blockDim.x + threadIdx.x;
    if (i < 2*B_*H_) { h[i] = 0.f; c[i] = 0.f; }
    if (i < B_*KA)   actbf[i] = __float2bfloat16(0.f);
    if (i < T_*B_)   alpha[i] = (i < B_) ? 1.f : 0.f;
}

/* ---------------- combined bf16 weight build, gate-interleaved rows ----------------
   wcomb row r' = 4*k + gate  <->  original row gate*H + k                           */
__global__ void build_wcomb(const float* __restrict__ W_ih, const float* __restrict__ W_hh,
                            __nv_bfloat16* __restrict__ wc) {
    size_t i = (size_t)blockIdx.x * blockDim.x + threadIdx.x;
    if (i >= (size_t)G4H * KA) return;
    int rp = (int)(i / KA), k = (int)(i % KA);
    int kk = rp >> 2, gate = rp & 3;
    int orig = gate * H_ + kk;
    float v = (k < E_) ? W_ih[(size_t)orig * (2*E_) + E_ + k]
                       : W_hh[(size_t)orig * H_ + (k - E_)];
    wc[i] = __float2bfloat16(v);
}

/* ---------------- embedding gather ---------------- */
__global__ void gather_emb(const float* __restrict__ emb_table,
                           const int* __restrict__ label,
                           float* __restrict__ emb) {
    int r = blockIdx.x;
    int n = label[r];
    const float* src = emb_table + (size_t)n * E_;
    float* dst = emb + (size_t)r * E_;
    for (int i = threadIdx.x; i < E_; i += blockDim.x) dst[i] = src[i];
}

/* ---------------- transpose (512,2048) -> (2048,512) ---------------- */
__global__ void transposeEH(const float* __restrict__ A, float* __restrict__ At) {
    __shared__ float tile[32][33];
    int x0 = blockIdx.x * 32, y0 = blockIdx.y * 32;
    int tx = threadIdx.x, ty = threadIdx.y;
    for (int j = 0; j < 32; j += 8)
        tile[ty+j][tx] = A[(size_t)(y0+ty+j) * H_ + x0 + tx];
    __syncthreads();
    for (int j = 0; j < 32; j += 8)
        At[(size_t)(x0+ty+j) * E_ + y0 + tx] = tile[tx][ty+j];
}

/* ============ tf32 tensor-core GEMM v3 (unchanged) ============ */
#define TKC 32
#define TKP (TKC+4)
__global__ __launch_bounds__(256) void tgemm_tn(
        const float* __restrict__ W, int ldw,
        const float* __restrict__ X, int ldx,
        const float* __restrict__ bias,
        float* __restrict__ C, size_t ldcw, size_t ldcx,
        int M, int Nx, int K)
{
    __shared__ unsigned Ws[128][TKP];
    __shared__ unsigned Xs[128][TKP];
    int tid = threadIdx.x;
    int wid = tid >> 5, lane = tid & 31;
    int wm = (wid & 3) * 32;
    int wn = (wid >> 2) * 64;
    int m0 = blockIdx.y * 128;
    int n0 = blockIdx.x * 128;
    int g = lane >> 2, t = lane & 3;

    int srow = tid >> 1, scol = (tid & 1) * 16;

    float c[2][8][4];
#pragma unroll
    for (int i = 0; i < 2; i++)
#pragma unroll
        for (int j = 0; j < 8; j++)
#pragma unroll
            for (int q = 0; q < 4; q++) c[i][j][q] = 0.f;

    for (int k0 = 0; k0 < K; k0 += TKC) {
#pragma unroll
        for (int i = 0; i < 4; i++) {
            float4 v = make_float4(0.f,0.f,0.f,0.f);
            if (m0 + srow < M)
                v = *(const float4*)(W + (size_t)(m0 + srow) * ldw + k0 + scol + i*4);
            Ws[srow][scol+i*4+0] = tf32c(v.x); Ws[srow][scol+i*4+1] = tf32c(v.y);
            Ws[srow][scol+i*4+2] = tf32c(v.z); Ws[srow][scol+i*4+3] = tf32c(v.w);
        }
#pragma unroll
        for (int i = 0; i < 4; i++) {
            float4 v = make_float4(0.f,0.f,0.f,0.f);
            if (n0 + srow < Nx)
                v = *(const float4*)(X + (size_t)(n0 + srow) * ldx + k0 + scol + i*4);
            Xs[srow][scol+i*4+0] = tf32c(v.x); Xs[srow][scol+i*4+1] = tf32c(v.y);
            Xs[srow][scol+i*4+2] = tf32c(v.z); Xs[srow][scol+i*4+3] = tf32c(v.w);
        }
        __syncthreads();

#pragma unroll
        for (int kk = 0; kk < TKC; kk += 8) {
            unsigned a[2][4];
#pragma unroll
            for (int mt = 0; mt < 2; mt++) {
                int br = wm + mt*16;
                a[mt][0] = Ws[br + g    ][kk + t];
                a[mt][1] = Ws[br + g + 8][kk + t];
                a[mt][2] = Ws[br + g    ][kk + t + 4];
                a[mt][3] = Ws[br + g + 8][kk + t + 4];
            }
            unsigned b[8][2];
#pragma unroll
            for (int nt = 0; nt < 8; nt++) {
                b[nt][0] = Xs[wn + nt*8 + g][kk + t];
                b[nt][1] = Xs[wn + nt*8 + g][kk + t + 4];
            }
#pragma unroll
            for (int mt = 0; mt < 2; mt++)
#pragma unroll
                for (int nt = 0; nt < 8; nt++) {
                    asm volatile(
                        "mma.sync.aligned.m16n8k8.row.col.f32.tf32.tf32.f32 "
                        "{%0,%1,%2,%3}, {%4,%5,%6,%7}, {%8,%9}, {%0,%1,%2,%3};"
                        : "+f"(c[mt][nt][0]), "+f"(c[mt][nt][1]),
                          "+f"(c[mt][nt][2]), "+f"(c[mt][nt][3])
                        : "r"(a[mt][0]), "r"(a[mt][1]), "r"(a[mt][2]), "r"(a[mt][3]),
                          "r"(b[nt][0]), "r"(b[nt][1]));
                }
        }
        __syncthreads();
    }

#pragma unroll
    for (int mt = 0; mt < 2; mt++) {
#pragma unroll
        for (int nt = 0; nt < 8; nt++) {
            int row0 = m0 + wm + mt*16 + g;
            int col0 = n0 + wn + nt*8 + 2*t;
#pragma unroll
            for (int half = 0; half < 2; half++) {
                int row = row0 + half*8;
                if (row >= M) continue;
                float bv = bias ? bias[row] : 0.f;
                if (col0 < Nx)
                    C[(size_t)row*ldcw + (size_t)col0*ldcx] = c[mt][nt][half*2+0] + bv;
                if (col0 + 1 < Nx)
                    C[(size_t)row*ldcw + (size_t)(col0+1)*ldcx] = c[mt][nt][half*2+1] + bv;
            }
        }
    }
}

/* ================ PERSISTENT DECODER LOOP: phases A+B fused ================ */
__global__ __launch_bounds__(NT) void decoder_loop(
        const float* __restrict__ x, const float* __restrict__ mask,
        const __nv_bfloat16* __restrict__ wcomb,
        const float* __restrict__ wproj, const float* __restrict__ comb,
        const float* __restrict__ eg,
        const float* __restrict__ v_m, const float* __restrict__ v_c,
        const float* __restrict__ r_m,
        const float* __restrict__ xh_m, const float* __restrict__ xh_c,
        float* hb, float* cb, float* alb,
        __nv_bfloat16* actbf,
        float* smv, float* scv, float* pv, float* uvv, float* betav,
        float* scall)
{
    extern __shared__ char dyn[];
    __nv_bfloat16* sACT = (__nv_bfloat16*)dyn;
    __nv_bfloat16* sWT  = sACT + 16*APAD;
    float*         sPART = (float*)sWT;     /* alias after final sync: [16][32] */

    __shared__ float shA[T_], shB[T_], shC[T_], shD[T_], shR[T_];
    int tid = threadIdx.x;
    int lane = tid & 31;
    int wid = tid >> 5;
    int gw = blockIdx.x * (NT/32) + wid;
    int NW = gridDim.x * (NT/32);
    int gtid = blockIdx.x * NT + tid;
    int NTH = gridDim.x * NT;
    int g = lane >> 2, t = lane & 3;

    int n0 = blockIdx.x * 32;           /* this block's 32 gate-interleaved rows */
    int nt = wid & 3;
    int khalf = wid >> 2;

    for (int u = 0; u < U_; u++) {
        float*       h_out = hb + ((u&1)^1)*(B_*H_);
        const float* c_in  = cb + (u&1)*(B_*H_);
        float*       c_out = cb + ((u&1)^1)*(B_*H_);
        const float* al_in  = alb + (u&1)*(T_*B_);
        float*       al_out = alb + ((u&1)^1)*(T_*B_);
        const float* eg_u = eg + (size_t)u*B_*G4H;
        float*       sc_u = scall + (size_t)u*B_*(2*E_);

        /* ---- Phase A+B: gates MMA + in-block LSTM pointwise ---- */
        for (int idx = tid; idx < 16*(KA/8); idx += NT) {
            int b = idx / (KA/8), f = idx % (KA/8);
            *(float4*)(sACT + (size_t)b*APAD + f*8) =
                *(const float4*)(actbf + (size_t)b*KA + f*8);
        }
        __syncthreads();

        float c0 = 0.f, c1 = 0.f, c2 = 0.f, c3 = 0.f;
        for (int it = 0; it < KHF/64; it++) {
            int kc = it * 64;
            for (int idx = tid; idx < 512; idx += NT) {
                int half = idx >> 8, row = (idx >> 3) & 31, f = idx & 7;
                *(float4*)(sWT + ((size_t)half*32 + row)*WPAD + f*8) =
                    *(const float4*)(wcomb + (size_t)(n0 + row)*KA + half*KHF + kc + f*8);
            }
            __syncthreads();

            const __nv_bfloat16* wrow = sWT + ((size_t)khalf*32 + nt*8 + g)*WPAD;
            const __nv_bfloat16* ar0 = sACT + (size_t)g*APAD + khalf*KHF + kc;
            const __nv_bfloat16* ar1 = sACT + (size_t)(g+8)*APAD + khalf*KHF + kc;
#pragma unroll
            for (int sub = 0; sub < 4; sub++) {
                int ks = sub*16;
                unsigned a0 = *(const unsigned*)(ar0 + ks + 2*t);
                unsigned a1 = *(const unsigned*)(ar1 + ks + 2*t);
                unsigned a2 = *(const unsigned*)(ar0 + ks + 2*t + 8);
                unsigned a3 = *(const unsigned*)(ar1 + ks + 2*t + 8);
                unsigned b0 = *(const unsigned*)(wrow + ks + 2*t);
                unsigned b1 = *(const unsigned*)(wrow + ks + 2*t + 8);
                asm volatile(
                    "mma.sync.aligned.m16n8k16.row.col.f32.bf16.bf16.f32 "
                    "{%0,%1,%2,%3}, {%4,%5,%6,%7}, {%8,%9}, {%0,%1,%2,%3};"
                    : "+f"(c0), "+f"(c1), "+f"(c2), "+f"(c3)
                    : "r"(a0), "r"(a1), "r"(a2), "r"(a3), "r"(b0), "r"(b1));
            }
            __syncthreads();
        }

        /* combine k-halves in smem: khalf1 stores, khalf0 adds */
        {
            int col = nt*8 + 2*t;
            if (khalf == 1) {
                sPART[g*32 + col]       = c0;
                sPART[g*32 + col + 1]   = c1;
                sPART[(g+8)*32 + col]     = c2;
                sPART[(g+8)*32 + col + 1] = c3;
            }
            __syncthreads();
            if (khalf == 0) {
                sPART[g*32 + col]       += c0;
                sPART[g*32 + col + 1]   += c1;
                sPART[(g+8)*32 + col]     += c2;
                sPART[(g+8)*32 + col + 1] += c3;
            }
            __syncthreads();
        }

        /* in-block LSTM: 128 threads, each handles (b, k_local) */
        if (tid < 128) {
            int b = tid >> 3, kl = tid & 7;
            int kglob = blockIdx.x * 8 + kl;
            float gi = sPART[b*32 + kl*4 + 0] + eg_u[(size_t)b*G4H + 0*H_ + kglob];
            float gf = sPART[b*32 + kl*4 + 1] + eg_u[(size_t)b*G4H + 1*H_ + kglob];
            float gg = sPART[b*32 + kl*4 + 2] + eg_u[(size_t)b*G4H + 2*H_ + kglob];
            float go = sPART[b*32 + kl*4 + 3] + eg_u[(size_t)b*G4H + 3*H_ + kglob];
            float cn = sigm(gf) * c_in[b*H_ + kglob] + sigm(gi) * tanhf(gg);
            c_out[b*H_ + kglob] = cn;
            float hn = sigm(go) * tanhf(cn);
            h_out[b*H_ + kglob] = hn;
            actbf[(size_t)b * KA + E_ + kglob] = __float2bfloat16(hn);
        }
        gbar();

        /* ---- Phase C: s / sm / sc (fp32) ---- */
        for (int r = gw; r < 3*E_; r += NW) {
            const float* Wr = (r < E_) ? (wproj + (size_t)r * H_)
                                       : (comb + (size_t)(r - E_) * H_);
            float acc[16];
#pragma unroll
            for (int b = 0; b < 16; b++) acc[b] = 0.f;
            for (int k = lane*4; k < H_; k += 128) {
                float4 wv = *(const float4*)(Wr + k);
#pragma unroll
                for (int b = 0; b < 16; b++) {
                    float4 a = *(const float4*)(h_out + (size_t)b*H_ + k);
                    acc[b] += wv.x*a.x + wv.y*a.y + wv.z*a.z + wv.w*a.w;
                }
            }
#pragma unroll
            for (int b = 0; b < 16; b++)
#pragma unroll
                for (int off = 16; off > 0; off >>= 1)
                    acc[b] += __shfl_xor_sync(0xffffffffu, acc[b], off);
            if (lane < 16) {
                float v = acc[lane];
                if (r < E_)            sc_u[lane*(2*E_) + r] = v;
                else if (r < 2*E_)     smv[lane*E_ + (r - E_)] = v;
                else                   scv[lane*E_ + (r - 2*E_)] = v;
            }
        }
        gbar();

        /* ---- Phase D: energies ---- */
        for (int w = gw; w < T_*B_; w += NW) {
            int tt = w >> 4, b = w & 15;
            const float* xmp = xh_m + (size_t)(tt*B_ + b) * E_;
            const float* xcp = xh_c + (size_t)(tt*B_ + b) * E_;
            const float* smp = smv + (size_t)b * E_;
            const float* scp = scv + (size_t)b * E_;
            float am = 0.f, ac = 0.f;
            for (int e = lane*4; e < E_; e += 128) {
                float4 a  = *(const float4*)(xmp + e);
                float4 s4 = *(const float4*)(smp + e);
                float4 v4 = *(const float4*)(v_m + e);
                float2 t01 = tanh2(a.x + s4.x, a.y + s4.y);
                float2 t23 = tanh2(a.z + s4.z, a.w + s4.w);
                am += v4.x*t01.x + v4.y*t01.y + v4.z*t23.x + v4.w*t23.y;

                float4 a2  = *(const float4*)(xcp + e);
                float4 s42 = *(const float4*)(scp + e);
                float4 v42 = *(const float4*)(v_c + e);
                float2 u01 = tanh2(a2.x + s42.x, a2.y + s42.y);
                float2 u23 = tanh2(a2.z + s42.z, a2.w + s42.w);
                ac += v42.x*u01.x + v42.y*u01.y + v42.z*u23.x + v42.w*u23.y;
            }
#pragma unroll
            for (int off = 16; off > 0; off >>= 1) {
                am += __shfl_xor_sync(0xffffffffu, am, off);
                ac += __shfl_xor_sync(0xffffffffu, ac, off);
            }
            if (lane == 0) {
                float mk = mask[b*T_ + tt];
                pv[tt*B_ + b] = sigm(am + r_m[0]) * mk;
                uvv[tt*B_ + b] = ac;
            }
        }
        gbar();

        /* ---- Phase E: per-b scans ---- */
        if (blockIdx.x < B_) {
            int b = blockIdx.x, tt = tid;
            float pvv = pv[tt*B_ + b];
            float uvl = uvv[tt*B_ + b];
            float ap  = al_in[tt*B_ + b];
            float mk  = mask[b*T_ + tt];

            shR[tt] = uvl; __syncthreads();
            for (int off = 128; off > 0; off >>= 1) {
                if (tt < off) shR[tt] = fmaxf(shR[tt], shR[tt+off]);
                __syncthreads();
            }
            float um = shR[0];

            float eu = expf(uvl - um) * mk;
            shA[tt] = eu; __syncthreads();
#pragma unroll
            for (int off = 1; off < T_; off <<= 1) {
                float xv = (tt >= off) ? shA[tt-off] : 0.f;
                __syncthreads(); shA[tt] += xv; __syncthreads();
            }
            float denom = shA[tt] - (tt >= 8 ? shA[tt-8] : 0.f);

            shB[tt] = 1.f - pvv; __syncthreads();
#pragma unroll
            for (int off = 1; off < T_; off <<= 1) {
                float xv = (tt >= off) ? shB[tt-off] : 1.f;
                __syncthreads(); shB[tt] *= xv; __syncthreads();
            }
            float cp = (tt == 0) ? 1.f : shB[tt-1];

            shC[tt] = ap / fmaxf(cp, EPS_); __syncthreads();
#pragma unroll
            for (int off = 1; off < T_; off <<= 1) {
                float xv = (tt >= off) ? shC[tt-off] : 0.f;
                __syncthreads(); shC[tt] += xv; __syncthreads();
            }
            float av = pvv * cp * shC[tt];

            shD[tt] = av / fmaxf(denom, EPS_); __syncthreads();
#pragma unroll
            for (int off = 1; off < T_; off <<= 1) {
                float xv = (tt >= off) ? shD[tt-off] : 0.f;
                __syncthreads(); shD[tt] += xv; __syncthreads();
            }
            int hi = (tt + 7 > T_-1) ? (T_-1) : (tt + 7);
            float bv = eu * (shD[hi] - (tt > 0 ? shD[tt-1] : 0.f));

            al_out[tt*B_ + b] = av;
            betav[tt*B_ + b] = bv;
        }
        gbar();

        /* ---- Phase F: ctx -> scall + actbf ---- */
        for (int i = gtid; i < B_*E_; i += NTH) {
            int b = i >> 9, d = i & (E_-1);
            const float* xp = x + (size_t)b*E_ + d;
            float acc = 0.f;
#pragma unroll 8
            for (int tq = 0; tq < T_; tq++)
                acc += betav[tq*B_ + b] * xp[(size_t)tq * B_ * E_];
            sc_u[(size_t)b*(2*E_) + E_ + d] = acc;
            actbf[(size_t)b * KA + d] = __float2bfloat16(acc);
        }
        gbar();
    }
}

/* ---------------- host launcher (serial, no stream objects) ---------------- */
extern "C" void kernel_launch(void* const* d_in, const int* in_sizes, int n_in,
                              void* d_out, int out_size)
{
    const float* x        = (const float*)d_in[0];
    const float* att_mask = (const float*)d_in[1];
    const float* emb_tab  = (const float*)d_in[2];
    const float* W_ih     = (const float*)d_in[3];
    const float* W_hh     = (const float*)d_in[4];
    const float* b_lstm   = (const float*)d_in[5];
    const float* W_proj   = (const float*)d_in[6];
    const float* Ws_m     = (const float*)d_in[7];
    const float* Wh_m     = (const float*)d_in[8];
    const float* v_m      = (const float*)d_in[9];
    const float* r_m      = (const float*)d_in[10];
    const float* Ws_c     = (const float*)d_in[11];
    const float* Wh_c     = (const float*)d_in[12];
    const float* v_c      = (const float*)d_in[13];
    const float* W_am     = (const float*)d_in[14];
    const float* W_lm     = (const float*)d_in[15];
    const int*   label    = (const int*)d_in[16];

    float* out_am = (float*)d_out;
    float* out_lm = out_am + (size_t)N_ * U_ * B_;

    float *xh_m, *xh_c, *emb, *eg, *hb, *cb, *alb, *sm, *sc, *p, *uu, *beta, *scall, *wpT, *comb;
    __nv_bfloat16 *wcomb, *actbf;
    cudaGetSymbolAddress((void**)&xh_m,  g_xh_m);
    cudaGetSymbolAddress((void**)&xh_c,  g_xh_c);
    cudaGetSymbolAddress((void**)&emb,   g_emb);
    cudaGetSymbolAddress((void**)&eg,    g_eg);
    cudaGetSymbolAddress((void**)&hb,    g_h);
    cudaGetSymbolAddress((void**)&cb,    g_c);
    cudaGetSymbolAddress((void**)&alb,   g_alpha);
    cudaGetSymbolAddress((void**)&sm,    g_sm);
    cudaGetSymbolAddress((void**)&sc,    g_sc);
    cudaGetSymbolAddress((void**)&p,     g_p);
    cudaGetSymbolAddress((void**)&uu,    g_u);
    cudaGetSymbolAddress((void**)&beta,  g_beta);
    cudaGetSymbolAddress((void**)&scall, g_scall);
    cudaGetSymbolAddress((void**)&wpT,   g_wpT);
    cudaGetSymbolAddress((void**)&comb,  g_comb);
    cudaGetSymbolAddress((void**)&wcomb, g_wcomb);
    cudaGetSymbolAddress((void**)&actbf, g_actbf);

    init_state<<<(2*B_*H_ + 255)/256, 256>>>(hb, cb, alb, actbf);

    {
        size_t n = (size_t)G4H * KA;
        build_wcomb<<<(int)((n + 511)/512), 512>>>(W_ih, W_hh, wcomb);
    }

    gather_emb<<<U_*B_, 128>>>(emb_tab, label, emb);

    /* encoder-side projections */
    tgemm_tn<<<dim3((T_*B_+127)/128, (E_+127)/128), 256>>>(Wh_m, E_, x, E_, nullptr,
            xh_m, 1, E_, E_, T_*B_, E_);
    tgemm_tn<<<dim3((T_*B_+127)/128, (E_+127)/128), 256>>>(Wh_c, E_, x, E_, nullptr,
            xh_c, 1, E_, E_, T_*B_, E_);

    /* eg = emb @ W_ih[:, :E]^T + b_lstm */
    tgemm_tn<<<dim3((U_*B_+127)/128, (G4H+127)/128), 256>>>(W_ih, 2*E_, emb, E_, b_lstm,
            eg, 1, G4H, G4H, U_*B_, E_);

    /* lm output */
    tgemm_tn<<<dim3((U_*B_+127)/128, (N_+127)/128), 256>>>(W_lm, E_, emb, E_, nullptr,
            out_lm, U_*B_, 1, N_, U_*B_, E_);

    /* folds: comb = [Ws_m@W_proj ; Ws_c@W_proj] */
    transposeEH<<<dim3(H_/32, E_/32), dim3(32, 8)>>>(W_proj, wpT);
    tgemm_tn<<<dim3((H_+127)/128, (E_+127)/128), 256>>>(Ws_m, E_, wpT, E_, nullptr,
            comb, H_, 1, E_, H_, E_);
    tgemm_tn<<<dim3((H_+127)/128, (E_+127)/128), 256>>>(Ws_c, E_, wpT, E_, nullptr,
            comb + (size_t)E_*H_, H_, 1, E_, H_, E_);

    /* 48-step recurrence in one persistent kernel */
    static int smem_set = 0;
    if (!smem_set) {
        cudaFuncSetAttribute(decoder_loop, cudaFuncAttributeMaxDynamicSharedMemorySize, SMEM_DYN);
        smem_set = 1;
    }
    decoder_loop<<<GRID, NT, SMEM_DYN>>>(x, att_mask, wcomb, W_proj, comb,
            eg, v_m, v_c, r_m, xh_m, xh_c,
            hb, cb, alb, actbf,
            sm, sc, p, uu, beta, scall);

    /* am output */
    tgemm_tn<<<dim3((U_*B_+127)/128, (N_+127)/128), 256>>>(W_am, 2*E_, scall, 2*E_, nullptr,
            out_am, U_*B_, 1, N_, U_*B_, 2*E_);
}